// round 3
// baseline (speedup 1.0000x reference)
#include <cuda_runtime.h>
#include <math.h>

#define NB 64
#define NV 50000
#define M_ROWS (NV*3)   // 150000
#define KS 300
#define KP 207

__constant__ int c_parent[23] = {0,0,0,1,2,3,4,5,6,7,8,9,9,9,12,13,14,16,17,18,19,20,21};

// Scratch (device globals; no allocation allowed)
__device__ float g_R[NB*24*9];
__device__ float g_lrot[NB*KP];
__device__ float g_vshaped[M_ROWS*NB];     // [row=(v*3+d)][b]
__device__ float g_J[NB*72];               // [b][j][d]
__device__ float g_G[NB*288];              // [b][j][12]  (3x4 row-major per joint)
#define NBLK_J 256
__device__ float g_Jpart[NBLK_J*4608];

// ---------------- K1: rodrigues -> R, lrotmin ----------------
__global__ void k_pose(const float* __restrict__ pose) {
    int b = blockIdx.x;
    int j = threadIdx.x;
    if (j < 24) {
        float t0 = pose[b*72 + j*3 + 0];
        float t1 = pose[b*72 + j*3 + 1];
        float t2 = pose[b*72 + j*3 + 2];
        float a0 = t0 + 1e-8f, a1 = t1 + 1e-8f, a2 = t2 + 1e-8f;
        float ang = sqrtf(a0*a0 + a1*a1 + a2*a2);
        float inv = 1.0f/ang;
        float half = 0.5f*ang;
        float s = sinf(half), c = cosf(half);
        float qw = c, qx = s*t0*inv, qy = s*t1*inv, qz = s*t2*inv;
        float qn = rsqrtf(qw*qw + qx*qx + qy*qy + qz*qz);
        qw *= qn; qx *= qn; qy *= qn; qz *= qn;
        float R[9];
        R[0] = qw*qw + qx*qx - qy*qy - qz*qz;
        R[1] = 2.f*(qx*qy - qw*qz);
        R[2] = 2.f*(qw*qy + qx*qz);
        R[3] = 2.f*(qw*qz + qx*qy);
        R[4] = qw*qw - qx*qx + qy*qy - qz*qz;
        R[5] = 2.f*(qy*qz - qw*qx);
        R[6] = 2.f*(qx*qz - qw*qy);
        R[7] = 2.f*(qw*qx + qy*qz);
        R[8] = qw*qw - qx*qx - qy*qy + qz*qz;
        #pragma unroll
        for (int e = 0; e < 9; e++) g_R[b*216 + j*9 + e] = R[e];
        if (j >= 1) {
            #pragma unroll
            for (int e = 0; e < 9; e++) {
                float d = (e == 0 || e == 4 || e == 8) ? 1.0f : 0.0f;
                g_lrot[b*207 + (j-1)*9 + e] = R[e] - d;
            }
        }
    }
}

// ---------------- K2: v_shaped GEMM (M=150000, K=300, N=64) ----------------
__global__ __launch_bounds__(256) void k_shape(const float* __restrict__ sd,
                                               const float* __restrict__ beta,
                                               const float* __restrict__ vt) {
    __shared__ float As[8][128];
    __shared__ float Bs[8][64];
    int tid = threadIdx.x;
    int row0 = blockIdx.x * 128;
    int tx = tid & 15, ty = tid >> 4;
    float acc[8][4];
    #pragma unroll
    for (int i = 0; i < 8; i++)
        #pragma unroll
        for (int j = 0; j < 4; j++) acc[i][j] = 0.f;

    for (int k0 = 0; k0 < KS; k0 += 8) {
        #pragma unroll
        for (int q = 0; q < 4; q++) {
            int l = tid + q*256;
            int r = l >> 3, k = l & 7;
            int row = row0 + r, kk = k0 + k;
            As[k][r] = (row < M_ROWS && kk < KS) ? sd[row*KS + kk] : 0.f;
        }
        #pragma unroll
        for (int q = 0; q < 2; q++) {
            int l = tid + q*256;
            int bc = l >> 3, k = l & 7;
            int kk = k0 + k;
            Bs[k][bc] = (kk < KS) ? beta[bc*KS + kk] : 0.f;
        }
        __syncthreads();
        #pragma unroll
        for (int k = 0; k < 8; k++) {
            float4 A0 = *(float4*)&As[k][ty*8];
            float4 A1 = *(float4*)&As[k][ty*8 + 4];
            float4 B0 = *(float4*)&Bs[k][tx*4];
            float a[8] = {A0.x, A0.y, A0.z, A0.w, A1.x, A1.y, A1.z, A1.w};
            float bb[4] = {B0.x, B0.y, B0.z, B0.w};
            #pragma unroll
            for (int i = 0; i < 8; i++)
                #pragma unroll
                for (int j = 0; j < 4; j++)
                    acc[i][j] = fmaf(a[i], bb[j], acc[i][j]);
        }
        __syncthreads();
    }
    #pragma unroll
    for (int i = 0; i < 8; i++) {
        int row = row0 + ty*8 + i;
        if (row < M_ROWS) {
            float t = vt[row];
            float4 o;
            o.x = acc[i][0] + t; o.y = acc[i][1] + t;
            o.z = acc[i][2] + t; o.w = acc[i][3] + t;
            *(float4*)&g_vshaped[row*64 + tx*4] = o;
        }
    }
}

// ---------------- K3: J split-K partials ----------------
__global__ __launch_bounds__(192) void k_joints(const float* __restrict__ Jr) {
    __shared__ float vsS[192*36];
    __shared__ float jrS[24*32];
    int tid = threadIdx.x;
    int bcol = tid & 63, d = tid >> 6;
    float acc[24];
    #pragma unroll
    for (int j = 0; j < 24; j++) acc[j] = 0.f;

    int nchunks = (NV + 31) / 32;
    for (int c = blockIdx.x; c < nchunks; c += gridDim.x) {
        int v0 = c * 32;
        int base = 3 * v0 * 64;
        #pragma unroll
        for (int q = 0; q < 32; q++) {
            int gi = base + q*192 + tid;
            vsS[tid*36 + q] = (gi < M_ROWS*64) ? g_vshaped[gi] : 0.f;
        }
        for (int i = tid; i < 768; i += 192) {
            int j = i >> 5, k = i & 31;
            jrS[i] = (v0 + k < NV) ? Jr[j*NV + v0 + k] : 0.f;
        }
        __syncthreads();
        #pragma unroll
        for (int kk = 0; kk < 8; kk++) {
            float4 v4 = *(float4*)&vsS[tid*36 + kk*4];
            #pragma unroll
            for (int j = 0; j < 24; j++) {
                float4 j4 = *(float4*)&jrS[j*32 + kk*4];
                acc[j] = fmaf(v4.x, j4.x, acc[j]);
                acc[j] = fmaf(v4.y, j4.y, acc[j]);
                acc[j] = fmaf(v4.z, j4.z, acc[j]);
                acc[j] = fmaf(v4.w, j4.w, acc[j]);
            }
        }
        __syncthreads();
    }
    #pragma unroll
    for (int j = 0; j < 24; j++)
        g_Jpart[blockIdx.x*4608 + bcol*72 + j*3 + d] = acc[j];
}

// ---------------- K3b: reduce J partials ----------------
__global__ void k_joints_reduce() {
    int idx = blockIdx.x * blockDim.x + threadIdx.x;
    if (idx < 4608) {
        float s = 0.f;
        for (int blk = 0; blk < NBLK_J; blk++) s += g_Jpart[blk*4608 + idx];
        g_J[idx] = s;
    }
}

// ---------------- K4: kinematic chain -> G' ----------------
__global__ void k_chain() {
    int b = blockIdx.x, lane = threadIdx.x;
    __shared__ float G[24][12];
    __shared__ float R[24][9];
    __shared__ float Jv[24][3];
    for (int i = lane; i < 216; i += 32) R[i/9][i%9] = g_R[b*216 + i];
    for (int i = lane; i < 72; i += 32) Jv[i/3][i%3] = g_J[b*72 + i];
    __syncwarp();
    for (int j = 0; j < 24; j++) {
        float val = 0.f;
        int m = lane >> 2, n = lane & 3;
        if (lane < 12) {
            if (j == 0) {
                val = (n < 3) ? R[0][m*3 + n] : Jv[0][m];
            } else {
                int p = c_parent[j-1];
                if (n < 3) {
                    val = G[p][m*4+0]*R[j][n] + G[p][m*4+1]*R[j][3+n] + G[p][m*4+2]*R[j][6+n];
                } else {
                    float t0 = Jv[j][0] - Jv[p][0];
                    float t1 = Jv[j][1] - Jv[p][1];
                    float t2 = Jv[j][2] - Jv[p][2];
                    val = G[p][m*4+0]*t0 + G[p][m*4+1]*t1 + G[p][m*4+2]*t2 + G[p][m*4+3];
                }
            }
        }
        __syncwarp();
        if (lane < 12) G[j][lane] = val;
        __syncwarp();
    }
    // G[...,3] -= G.R @ J_abs
    for (int i = lane; i < 72; i += 32) {
        int j = i / 3, m = i % 3;
        float c = G[j][m*4+0]*Jv[j][0] + G[j][m*4+1]*Jv[j][1] + G[j][m*4+2]*Jv[j][2];
        G[j][m*4+3] -= c;
    }
    __syncwarp();
    for (int i = lane; i < 288; i += 32) g_G[b*288 + i] = G[i/12][i%12];
}

// ---------------- K5: pose-blend GEMM + skinning, fused ----------------
// smem layout (floats): Gs[18432] ws[800] ps[96*65] As[8*96] Bs[8*64] = 26752
#define K5_SMEM_FLOATS 26752
__global__ __launch_bounds__(256) void k_pose_skin(const float* __restrict__ pd,
                                                   const float* __restrict__ wts,
                                                   float* __restrict__ out) {
    extern __shared__ float sm[];
    float* Gs = sm;
    float* ws = sm + 18432;
    float* ps = sm + 19232;
    float* As = sm + 25472;
    float* Bs = sm + 26240;
    int tid = threadIdx.x;
    int v0 = blockIdx.x * 32;
    int row0 = v0 * 3;

    {   // stage all G (64 batches x 24 joints x 12) into smem
        float4* dst = (float4*)Gs;
        const float4* src = (const float4*)g_G;
        for (int i = tid; i < 4608; i += 256) dst[i] = src[i];
    }
    for (int i = tid; i < 768; i += 256) {
        int vl = i / 24, j = i % 24;
        int v = v0 + vl;
        ws[vl*25 + j] = (v < NV) ? wts[v*24 + j] : 0.f;
    }

    int tx = tid & 15, ty = tid >> 4;
    float acc[6][4];
    #pragma unroll
    for (int i = 0; i < 6; i++)
        #pragma unroll
        for (int j = 0; j < 4; j++) acc[i][j] = 0.f;

    for (int k0 = 0; k0 < KP; k0 += 8) {
        #pragma unroll
        for (int q = 0; q < 3; q++) {
            int l = tid + q*256;
            int r = l >> 3, k = l & 7;
            int row = row0 + r, kk = k0 + k;
            As[k*96 + r] = (row < M_ROWS && kk < KP) ? pd[row*KP + kk] : 0.f;
        }
        #pragma unroll
        for (int q = 0; q < 2; q++) {
            int l = tid + q*256;
            int bc = l >> 3, k = l & 7;
            int kk = k0 + k;
            Bs[k*64 + bc] = (kk < KP) ? g_lrot[bc*207 + kk] : 0.f;
        }
        __syncthreads();
        #pragma unroll
        for (int k = 0; k < 8; k++) {
            float a[6];
            #pragma unroll
            for (int i = 0; i < 6; i++) a[i] = As[k*96 + ty*6 + i];
            float4 B0 = *(float4*)&Bs[k*64 + tx*4];
            float bb[4] = {B0.x, B0.y, B0.z, B0.w};
            #pragma unroll
            for (int i = 0; i < 6; i++)
                #pragma unroll
                for (int j = 0; j < 4; j++)
                    acc[i][j] = fmaf(a[i], bb[j], acc[i][j]);
        }
        __syncthreads();
    }

    // epilogue: v_posed = GEMM + v_shaped -> ps
    #pragma unroll
    for (int i = 0; i < 6; i++) {
        int rl = ty*6 + i;
        int row = row0 + rl;
        float4 vs = {0.f, 0.f, 0.f, 0.f};
        if (row < M_ROWS) vs = *(const float4*)&g_vshaped[row*64 + tx*4];
        ps[rl*65 + tx*4 + 0] = acc[i][0] + vs.x;
        ps[rl*65 + tx*4 + 1] = acc[i][1] + vs.y;
        ps[rl*65 + tx*4 + 2] = acc[i][2] + vs.z;
        ps[rl*65 + tx*4 + 3] = acc[i][3] + vs.w;
    }
    __syncthreads();

    // skinning: 2048 (vertex, batch) pairs, 8 per thread
    #pragma unroll
    for (int pp = 0; pp < 8; pp++) {
        int p = tid + pp*256;
        int vl = p & 31, b = p >> 5;
        int v = v0 + vl;
        if (v < NV) {
            float x = ps[(vl*3 + 0)*65 + b];
            float y = ps[(vl*3 + 1)*65 + b];
            float z = ps[(vl*3 + 2)*65 + b];
            float T[12];
            #pragma unroll
            for (int e = 0; e < 12; e++) T[e] = 0.f;
            const float4* Gb = (const float4*)(Gs + b*288);
            #pragma unroll
            for (int j = 0; j < 24; j++) {
                float wj = ws[vl*25 + j];
                float4 g0 = Gb[j*3 + 0];
                float4 g1 = Gb[j*3 + 1];
                float4 g2 = Gb[j*3 + 2];
                T[0] = fmaf(wj, g0.x, T[0]);  T[1] = fmaf(wj, g0.y, T[1]);
                T[2] = fmaf(wj, g0.z, T[2]);  T[3] = fmaf(wj, g0.w, T[3]);
                T[4] = fmaf(wj, g1.x, T[4]);  T[5] = fmaf(wj, g1.y, T[5]);
                T[6] = fmaf(wj, g1.z, T[6]);  T[7] = fmaf(wj, g1.w, T[7]);
                T[8] = fmaf(wj, g2.x, T[8]);  T[9] = fmaf(wj, g2.y, T[9]);
                T[10] = fmaf(wj, g2.z, T[10]); T[11] = fmaf(wj, g2.w, T[11]);
            }
            float ox = T[0]*x + T[1]*y + T[2]*z + T[3];
            float oy = T[4]*x + T[5]*y + T[6]*z + T[7];
            float oz = T[8]*x + T[9]*y + T[10]*z + T[11];
            int o = b*(NV*3) + v*3;
            out[o + 0] = ox;
            out[o + 1] = oy;
            out[o + 2] = oz;
        }
    }
}

extern "C" void kernel_launch(void* const* d_in, const int* in_sizes, int n_in,
                              void* d_out, int out_size) {
    const float* pose = (const float*)d_in[0];
    const float* beta = (const float*)d_in[1];
    const float* vt   = (const float*)d_in[2];
    const float* sd   = (const float*)d_in[3];
    const float* pd   = (const float*)d_in[4];
    const float* Jr   = (const float*)d_in[5];
    const float* wts  = (const float*)d_in[6];
    float* out = (float*)d_out;

    cudaFuncSetAttribute(k_pose_skin, cudaFuncAttributeMaxDynamicSharedMemorySize,
                         K5_SMEM_FLOATS * (int)sizeof(float));

    k_pose<<<NB, 32>>>(pose);
    k_shape<<<(M_ROWS + 127)/128, 256>>>(sd, beta, vt);
    k_joints<<<NBLK_J, 192>>>(Jr);
    k_joints_reduce<<<(4608 + 255)/256, 256>>>();
    k_chain<<<NB, 32>>>();
    k_pose_skin<<<(NV + 31)/32, 256, K5_SMEM_FLOATS * (int)sizeof(float)>>>(pd, wts, out);
}

// round 6
// speedup vs baseline: 1.3619x; 1.3619x over previous
#include <cuda_runtime.h>
#include <math.h>
#include <stdint.h>

#define NB 64
#define NV 50000
#define M_ROWS (NV*3)   // 150000
#define KS 300
#define KP 207

__constant__ int c_parent[23] = {0,0,0,1,2,3,4,5,6,7,8,9,9,9,12,13,14,16,17,18,19,20,21};

// Scratch (device globals; no allocation allowed)
__device__ float g_R[NB*24*9];
__device__ float g_lrot[NB*KP];
__device__ float g_vshaped[M_ROWS*NB];     // [row=(v*3+d)][b]
__device__ float g_J[NB*72];               // [b][j][d]
__device__ float g_G[NB*288];              // [b][j][12]  (3x4 row-major per joint)
#define NBLK_J 256
__device__ float g_Jpart[NBLK_J*4608];

// -------- helpers: tf32 convert + m16n8k8 mma --------
__device__ __forceinline__ float to_tf32(float x) {
    uint32_t u;
    asm("cvt.rna.tf32.f32 %0, %1;" : "=r"(u) : "f"(x));
    return __uint_as_float(u);
}

__device__ __forceinline__ void mma_tf32(float* d,
                                         const uint32_t* a,
                                         const uint32_t* b) {
    asm volatile(
        "mma.sync.aligned.m16n8k8.row.col.f32.tf32.tf32.f32 "
        "{%0,%1,%2,%3}, {%4,%5,%6,%7}, {%8,%9}, {%0,%1,%2,%3};\n"
        : "+f"(d[0]), "+f"(d[1]), "+f"(d[2]), "+f"(d[3])
        : "r"(a[0]), "r"(a[1]), "r"(a[2]), "r"(a[3]),
          "r"(b[0]), "r"(b[1]));
}

// ---------------- K1: rodrigues -> R, lrotmin ----------------
__global__ void k_pose(const float* __restrict__ pose) {
    int b = blockIdx.x;
    int j = threadIdx.x;
    if (j < 24) {
        float t0 = pose[b*72 + j*3 + 0];
        float t1 = pose[b*72 + j*3 + 1];
        float t2 = pose[b*72 + j*3 + 2];
        float a0 = t0 + 1e-8f, a1 = t1 + 1e-8f, a2 = t2 + 1e-8f;
        float ang = sqrtf(a0*a0 + a1*a1 + a2*a2);
        float inv = 1.0f/ang;
        float half = 0.5f*ang;
        float s = sinf(half), c = cosf(half);
        float qw = c, qx = s*t0*inv, qy = s*t1*inv, qz = s*t2*inv;
        float qn = rsqrtf(qw*qw + qx*qx + qy*qy + qz*qz);
        qw *= qn; qx *= qn; qy *= qn; qz *= qn;
        float R[9];
        R[0] = qw*qw + qx*qx - qy*qy - qz*qz;
        R[1] = 2.f*(qx*qy - qw*qz);
        R[2] = 2.f*(qw*qy + qx*qz);
        R[3] = 2.f*(qw*qz + qx*qy);
        R[4] = qw*qw - qx*qx + qy*qy - qz*qz;
        R[5] = 2.f*(qy*qz - qw*qx);
        R[6] = 2.f*(qx*qz - qw*qy);
        R[7] = 2.f*(qw*qx + qy*qz);
        R[8] = qw*qw - qx*qx - qy*qy + qz*qz;
        #pragma unroll
        for (int e = 0; e < 9; e++) g_R[b*216 + j*9 + e] = R[e];
        if (j >= 1) {
            #pragma unroll
            for (int e = 0; e < 9; e++) {
                float d = (e == 0 || e == 4 || e == 8) ? 1.0f : 0.0f;
                g_lrot[b*207 + (j-1)*9 + e] = R[e] - d;
            }
        }
    }
}

// ---------------- K2: v_shaped GEMM via tf32 MMA ----------------
// C[150000 x 64] = sd[150000 x 300] * beta^T[300 x 64] (+ vt broadcast)
// Block: 256 thr = 8 warps (4 m x 2 n), tile 128m x 64n, kTile 16.
__global__ __launch_bounds__(256) void k_shape(const float* __restrict__ sd,
                                               const float* __restrict__ beta,
                                               const float* __restrict__ vt) {
    __shared__ float As[16][136];   // stride 136 (%32==8) -> conflict-free frags
    __shared__ float Bs[16][72];    // stride 72  (%32==8)
    int tid = threadIdx.x;
    int warp = tid >> 5, lane = tid & 31;
    int gid = lane >> 2, tg = lane & 3;
    int wm = warp >> 1, wn = warp & 1;
    int row0 = blockIdx.x * 128;

    float acc[2][4][4];
    #pragma unroll
    for (int mi = 0; mi < 2; mi++)
        #pragma unroll
        for (int ni = 0; ni < 4; ni++)
            #pragma unroll
            for (int e = 0; e < 4; e++) acc[mi][ni][e] = 0.f;

    int r = tid & 127, half = tid >> 7;       // A staging: row r, k-half
    bool rowok = (row0 + r) < M_ROWS;
    const float* srow = sd + (size_t)(row0 + r) * KS;
    int bcs = tid & 63, kqs = tid >> 6;        // B staging

    for (int k0 = 0; k0 < KS; k0 += 16) {
        // stage A: 128 rows x 16 k (fp32 -> tf32)
        #pragma unroll
        for (int q = 0; q < 2; q++) {
            int kk = k0 + half*8 + q*4;
            float4 v = make_float4(0.f,0.f,0.f,0.f);
            if (rowok && kk < KS) v = *(const float4*)(srow + kk);
            As[half*8 + q*4 + 0][r] = to_tf32(v.x);
            As[half*8 + q*4 + 1][r] = to_tf32(v.y);
            As[half*8 + q*4 + 2][r] = to_tf32(v.z);
            As[half*8 + q*4 + 3][r] = to_tf32(v.w);
        }
        // stage B: 16 k x 64 batches
        {
            int kk = k0 + kqs*4;
            float4 v = make_float4(0.f,0.f,0.f,0.f);
            if (kk < KS) v = *(const float4*)(beta + bcs*KS + kk);
            Bs[kqs*4 + 0][bcs] = to_tf32(v.x);
            Bs[kqs*4 + 1][bcs] = to_tf32(v.y);
            Bs[kqs*4 + 2][bcs] = to_tf32(v.z);
            Bs[kqs*4 + 3][bcs] = to_tf32(v.w);
        }
        __syncthreads();
        #pragma unroll
        for (int k8 = 0; k8 < 16; k8 += 8) {
            uint32_t a[2][4], b[4][2];
            #pragma unroll
            for (int mi = 0; mi < 2; mi++) {
                int rr = wm*32 + mi*16 + gid;
                a[mi][0] = __float_as_uint(As[k8 + tg    ][rr]);
                a[mi][1] = __float_as_uint(As[k8 + tg    ][rr + 8]);
                a[mi][2] = __float_as_uint(As[k8 + tg + 4][rr]);
                a[mi][3] = __float_as_uint(As[k8 + tg + 4][rr + 8]);
            }
            #pragma unroll
            for (int ni = 0; ni < 4; ni++) {
                int cc = wn*32 + ni*8 + gid;
                b[ni][0] = __float_as_uint(Bs[k8 + tg    ][cc]);
                b[ni][1] = __float_as_uint(Bs[k8 + tg + 4][cc]);
            }
            #pragma unroll
            for (int mi = 0; mi < 2; mi++)
                #pragma unroll
                for (int ni = 0; ni < 4; ni++)
                    mma_tf32(acc[mi][ni], a[mi], b[ni]);
        }
        __syncthreads();
    }

    // epilogue: += v_template broadcast, write [row][64]
    #pragma unroll
    for (int mi = 0; mi < 2; mi++) {
        int rowa = row0 + wm*32 + mi*16 + gid;
        int rowb = rowa + 8;
        #pragma unroll
        for (int ni = 0; ni < 4; ni++) {
            int col = wn*32 + ni*8 + tg*2;
            if (rowa < M_ROWS) {
                float t = vt[rowa];
                float2 o = make_float2(acc[mi][ni][0] + t, acc[mi][ni][1] + t);
                *(float2*)&g_vshaped[rowa*64 + col] = o;
            }
            if (rowb < M_ROWS) {
                float t = vt[rowb];
                float2 o = make_float2(acc[mi][ni][2] + t, acc[mi][ni][3] + t);
                *(float2*)&g_vshaped[rowb*64 + col] = o;
            }
        }
    }
}

// ---------------- K3: J split-K partials ----------------
__global__ __launch_bounds__(192) void k_joints(const float* __restrict__ Jr) {
    __shared__ float vsS[192*36];
    __shared__ float jrS[24*32];
    int tid = threadIdx.x;
    int bcol = tid & 63, d = tid >> 6;
    float acc[24];
    #pragma unroll
    for (int j = 0; j < 24; j++) acc[j] = 0.f;

    int nchunks = (NV + 31) / 32;
    for (int c = blockIdx.x; c < nchunks; c += gridDim.x) {
        int v0 = c * 32;
        int base = 3 * v0 * 64;
        #pragma unroll
        for (int q = 0; q < 32; q++) {
            int gi = base + q*192 + tid;
            vsS[tid*36 + q] = (gi < M_ROWS*64) ? g_vshaped[gi] : 0.f;
        }
        for (int i = tid; i < 768; i += 192) {
            int j = i >> 5, k = i & 31;
            jrS[i] = (v0 + k < NV) ? Jr[j*NV + v0 + k] : 0.f;
        }
        __syncthreads();
        #pragma unroll
        for (int kk = 0; kk < 8; kk++) {
            float4 v4 = *(float4*)&vsS[tid*36 + kk*4];
            #pragma unroll
            for (int j = 0; j < 24; j++) {
                float4 j4 = *(float4*)&jrS[j*32 + kk*4];
                acc[j] = fmaf(v4.x, j4.x, acc[j]);
                acc[j] = fmaf(v4.y, j4.y, acc[j]);
                acc[j] = fmaf(v4.z, j4.z, acc[j]);
                acc[j] = fmaf(v4.w, j4.w, acc[j]);
            }
        }
        __syncthreads();
    }
    #pragma unroll
    for (int j = 0; j < 24; j++)
        g_Jpart[blockIdx.x*4608 + bcol*72 + j*3 + d] = acc[j];
}

// ---------------- K3b: reduce J partials (parallel, coalesced) ----------------
__global__ __launch_bounds__(256) void k_joints_reduce() {
    __shared__ float part[8][32];
    int idx = blockIdx.x * 32 + (threadIdx.x & 31);
    int seg = threadIdx.x >> 5;
    float s = 0.f;
    #pragma unroll
    for (int q = 0; q < 32; q++) {
        int blk = seg*32 + q;
        s += g_Jpart[blk*4608 + idx];
    }
    part[seg][threadIdx.x & 31] = s;
    __syncthreads();
    if (seg == 0) {
        float t = part[0][threadIdx.x & 31];
        #pragma unroll
        for (int q = 1; q < 8; q++) t += part[q][threadIdx.x & 31];
        g_J[idx] = t;
    }
}

// ---------------- K4: kinematic chain -> G' ----------------
__global__ void k_chain() {
    int b = blockIdx.x, lane = threadIdx.x;
    __shared__ float G[24][12];
    __shared__ float R[24][9];
    __shared__ float Jv[24][3];
    for (int i = lane; i < 216; i += 32) R[i/9][i%9] = g_R[b*216 + i];
    for (int i = lane; i < 72; i += 32) Jv[i/3][i%3] = g_J[b*72 + i];
    __syncwarp();
    for (int j = 0; j < 24; j++) {
        float val = 0.f;
        int m = lane >> 2, n = lane & 3;
        if (lane < 12) {
            if (j == 0) {
                val = (n < 3) ? R[0][m*3 + n] : Jv[0][m];
            } else {
                int p = c_parent[j-1];
                if (n < 3) {
                    val = G[p][m*4+0]*R[j][n] + G[p][m*4+1]*R[j][3+n] + G[p][m*4+2]*R[j][6+n];
                } else {
                    float t0 = Jv[j][0] - Jv[p][0];
                    float t1 = Jv[j][1] - Jv[p][1];
                    float t2 = Jv[j][2] - Jv[p][2];
                    val = G[p][m*4+0]*t0 + G[p][m*4+1]*t1 + G[p][m*4+2]*t2 + G[p][m*4+3];
                }
            }
        }
        __syncwarp();
        if (lane < 12) G[j][lane] = val;
        __syncwarp();
    }
    for (int i = lane; i < 72; i += 32) {
        int j = i / 3, m = i % 3;
        float c = G[j][m*4+0]*Jv[j][0] + G[j][m*4+1]*Jv[j][1] + G[j][m*4+2]*Jv[j][2];
        G[j][m*4+3] -= c;
    }
    __syncwarp();
    for (int i = lane; i < 288; i += 32) g_G[b*288 + i] = G[i/12][i%12];
}

// ---------------- K5: pose-blend GEMM (tf32 MMA) + skinning, fused ----------------
// Block: 192 thr = 6 warps (3 m x 2 n). Tile: 96 rows (32 vertices) x 64 batches.
// smem floats: Gs[18432] ws[800] ps[96*65=6240] As[16*104=1664] Bs[16*72=1152] = 28288
#define K5_SMEM_FLOATS 28288
__global__ __launch_bounds__(192) void k_pose_skin(const float* __restrict__ pd,
                                                   const float* __restrict__ wts,
                                                   float* __restrict__ out) {
    extern __shared__ float sm[];
    float* Gs = sm;                    // 18432
    float* ws = sm + 18432;            // 800
    float* ps = sm + 19232;            // 6240
    float (*As)[104] = (float(*)[104])(sm + 25472);  // 16 x 104
    float (*Bs)[72]  = (float(*)[72]) (sm + 27136);  // 16 x 72
    int tid = threadIdx.x;
    int warp = tid >> 5, lane = tid & 31;
    int gid = lane >> 2, tg = lane & 3;
    int wm = warp >> 1, wn = warp & 1;
    int v0 = blockIdx.x * 32;
    int row0 = v0 * 3;

    {   // stage all G (64 b x 24 j x 12) into smem
        float4* dst = (float4*)Gs;
        const float4* src = (const float4*)g_G;
        for (int i = tid; i < 4608; i += 192) dst[i] = src[i];
    }
    for (int i = tid; i < 768; i += 192) {
        int vl = i / 24, j = i % 24;
        int v = v0 + vl;
        ws[vl*25 + j] = (v < NV) ? wts[v*24 + j] : 0.f;
    }

    float acc[2][4][4];
    #pragma unroll
    for (int mi = 0; mi < 2; mi++)
        #pragma unroll
        for (int ni = 0; ni < 4; ni++)
            #pragma unroll
            for (int e = 0; e < 4; e++) acc[mi][ni][e] = 0.f;

    int r = tid % 96, half = tid / 96;     // A staging
    bool rowok = (row0 + r) < M_ROWS;
    const float* prow = pd + (size_t)(row0 + r) * KP;
    int bcs = tid & 63, khs = tid >> 6;    // B staging (tid<128 active)

    for (int k0 = 0; k0 < KP; k0 += 16) {
        #pragma unroll
        for (int i = 0; i < 8; i++) {
            int kk = k0 + half*8 + i;
            float v = (rowok && kk < KP) ? prow[kk] : 0.f;
            As[half*8 + i][r] = to_tf32(v);
        }
        if (tid < 128) {
            #pragma unroll
            for (int i = 0; i < 8; i++) {
                int kk = k0 + khs*8 + i;
                float v = (kk < KP) ? g_lrot[bcs*KP + kk] : 0.f;
                Bs[khs*8 + i][bcs] = to_tf32(v);
            }
        }
        __syncthreads();
        #pragma unroll
        for (int k8 = 0; k8 < 16; k8 += 8) {
            uint32_t a[2][4], b[4][2];
            #pragma unroll
            for (int mi = 0; mi < 2; mi++) {
                int rr = wm*32 + mi*16 + gid;
                a[mi][0] = __float_as_uint(As[k8 + tg    ][rr]);
                a[mi][1] = __float_as_uint(As[k8 + tg    ][rr + 8]);
                a[mi][2] = __float_as_uint(As[k8 + tg + 4][rr]);
                a[mi][3] = __float_as_uint(As[k8 + tg + 4][rr + 8]);
            }
            #pragma unroll
            for (int ni = 0; ni < 4; ni++) {
                int cc = wn*32 + ni*8 + gid;
                b[ni][0] = __float_as_uint(Bs[k8 + tg    ][cc]);
                b[ni][1] = __float_as_uint(Bs[k8 + tg + 4][cc]);
            }
            #pragma unroll
            for (int mi = 0; mi < 2; mi++)
                #pragma unroll
                for (int ni = 0; ni < 4; ni++)
                    mma_tf32(acc[mi][ni], a[mi], b[ni]);
        }
        __syncthreads();
    }

    // epilogue: v_posed = GEMM + v_shaped -> ps[row][65]
    #pragma unroll
    for (int mi = 0; mi < 2; mi++) {
        #pragma unroll
        for (int half8 = 0; half8 < 2; half8++) {
            int rl = wm*32 + mi*16 + half8*8 + gid;
            int row = row0 + rl;
            #pragma unroll
            for (int ni = 0; ni < 4; ni++) {
                int col = wn*32 + ni*8 + tg*2;
                float2 vs = make_float2(0.f, 0.f);
                if (row < M_ROWS) vs = *(const float2*)&g_vshaped[row*64 + col];
                ps[rl*65 + col    ] = acc[mi][ni][half8*2 + 0] + vs.x;
                ps[rl*65 + col + 1] = acc[mi][ni][half8*2 + 1] + vs.y;
            }
        }
    }
    __syncthreads();

    // skinning: 2048 (vertex, batch) pairs; b uniform within each warp (G broadcast)
    for (int p = tid; p < 2048; p += 192) {
        int vl = p & 31, b = p >> 5;
        int v = v0 + vl;
        if (v < NV) {
            float x = ps[(vl*3 + 0)*65 + b];
            float y = ps[(vl*3 + 1)*65 + b];
            float z = ps[(vl*3 + 2)*65 + b];
            float T[12];
            #pragma unroll
            for (int e = 0; e < 12; e++) T[e] = 0.f;
            const float4* Gb = (const float4*)(Gs + b*288);
            #pragma unroll
            for (int j = 0; j < 24; j++) {
                float wj = ws[vl*25 + j];
                float4 g0 = Gb[j*3 + 0];
                float4 g1 = Gb[j*3 + 1];
                float4 g2 = Gb[j*3 + 2];
                T[0] = fmaf(wj, g0.x, T[0]);  T[1] = fmaf(wj, g0.y, T[1]);
                T[2] = fmaf(wj, g0.z, T[2]);  T[3] = fmaf(wj, g0.w, T[3]);
                T[4] = fmaf(wj, g1.x, T[4]);  T[5] = fmaf(wj, g1.y, T[5]);
                T[6] = fmaf(wj, g1.z, T[6]);  T[7] = fmaf(wj, g1.w, T[7]);
                T[8] = fmaf(wj, g2.x, T[8]);  T[9] = fmaf(wj, g2.y, T[9]);
                T[10] = fmaf(wj, g2.z, T[10]); T[11] = fmaf(wj, g2.w, T[11]);
            }
            float ox = T[0]*x + T[1]*y + T[2]*z + T[3];
            float oy = T[4]*x + T[5]*y + T[6]*z + T[7];
            float oz = T[8]*x + T[9]*y + T[10]*z + T[11];
            int o = b*(NV*3) + v*3;
            out[o + 0] = ox;
            out[o + 1] = oy;
            out[o + 2] = oz;
        }
    }
}

extern "C" void kernel_launch(void* const* d_in, const int* in_sizes, int n_in,
                              void* d_out, int out_size) {
    const float* pose = (const float*)d_in[0];
    const float* beta = (const float*)d_in[1];
    const float* vt   = (const float*)d_in[2];
    const float* sd   = (const float*)d_in[3];
    const float* pd   = (const float*)d_in[4];
    const float* Jr   = (const float*)d_in[5];
    const float* wts  = (const float*)d_in[6];
    float* out = (float*)d_out;

    cudaFuncSetAttribute(k_pose_skin, cudaFuncAttributeMaxDynamicSharedMemorySize,
                         K5_SMEM_FLOATS * (int)sizeof(float));

    k_pose<<<NB, 32>>>(pose);
    k_shape<<<(M_ROWS + 127)/128, 256>>>(sd, beta, vt);
    k_joints<<<NBLK_J, 192>>>(Jr);
    k_joints_reduce<<<144, 256>>>();
    k_chain<<<NB, 32>>>();
    k_pose_skin<<<(NV + 31)/32, 192, K5_SMEM_FLOATS * (int)sizeof(float)>>>(pd, wts, out);
}